// round 1
// baseline (speedup 1.0000x reference)
#include <cuda_runtime.h>

// ----------------------------------------------------------------------------
// FBP pipeline:
//   K0: tables  — exact ramp-filter impulse response (fp64), cos/sin tables
//   K1: filter  — circular conv of the 16 BASE frames (filter ∘ lerp = lerp ∘ filter)
//   K2: backproject — per-slice: lerp 16 frames -> 128 angle rows in smem
//                     (guard-padded), then direct backprojection, fp32 exact.
// ----------------------------------------------------------------------------

#define MPI 3.14159265358979323846

__device__ float g_hker[128];                    // ramp filter IR * (pi/128)
__device__ float g_cos[128];
__device__ float g_sin[128];
__device__ float g_Fbase[16 * 1024 * 128];       // filtered base frames, 8 MB

// --------------------------- K0: tables -------------------------------------
__global__ void k_tables() {
    int n = threadIdx.x;
    if (n < 128) {
        double s = 0.0;
        for (int m = 0; m < 128; m++) {
            double f = (double)(m < 64 ? m : 128 - m) / 128.0;
            int ph = (m * n) & 127;              // exact periodic phase
            s += f * cos(2.0 * MPI * (double)ph / 128.0);
        }
        g_hker[n] = (float)((s / 128.0) * (MPI / 128.0));
        double th = MPI * (double)n / 128.0;
        g_cos[n] = (float)cos(th);
        g_sin[n] = (float)sin(th);
    }
}

// --------------------------- K1: filter -------------------------------------
// One warp per row (t,c,h): F[j] = sum_k p[k] * h[(j-k) mod 128]
__global__ __launch_bounds__(256) void k_filter(const float* __restrict__ feat) {
    __shared__ float hk[256];                    // hker duplicated: hk[i]=h[i&127]
    int tid = threadIdx.x;
    hk[tid] = g_hker[tid & 127];
    __syncthreads();

    int lane = tid & 31;
    int wid  = tid >> 5;
    int r = blockIdx.x * 8 + wid;                // row 0..16383
    const float* row = feat + (size_t)r * 128;

    float rv[4];
    rv[0] = row[lane];      rv[1] = row[lane + 32];
    rv[2] = row[lane + 64]; rv[3] = row[lane + 96];
    float a0 = 0.f, a1 = 0.f, a2 = 0.f, a3 = 0.f;

#pragma unroll
    for (int kb = 0; kb < 4; kb++) {
        float rsel = rv[kb];
#pragma unroll
        for (int kk = 0; kk < 32; kk++) {
            float x = __shfl_sync(0xffffffffu, rsel, kk);
            int base = lane + 128 - (kb * 32 + kk);   // in [1,255]
            a0 += x * hk[base];
            a1 += x * hk[base + 32];
            a2 += x * hk[base + 64];
            a3 += x * hk[base + 96];
        }
    }
    float* o = g_Fbase + (size_t)r * 128;
    o[lane] = a0; o[lane + 32] = a1; o[lane + 64] = a2; o[lane + 96] = a3;
}

// ------------------------ K2: backprojection --------------------------------
// grid = 1024 slices; 256 threads; dynamic smem = FA[128 angles][192] fp32
// (32-wide zero guards on both sides kill all bounds checks).
extern __shared__ float s_FA[];

__global__ __launch_bounds__(256, 2) void k_bp(float* __restrict__ out) {
    __shared__ float sc[128], ss[128];
    float (*FA)[192] = (float (*)[192])s_FA;

    int tid = threadIdx.x;
    int s   = blockIdx.x;                        // slice = c*128 + h

    if (tid < 128) { sc[tid] = g_cos[tid]; ss[tid] = g_sin[tid]; }

    // zero the guard bands: 128 angles x (32 left + 32 right)
    for (int g = tid; g < 8192; g += 256) {
        int a = g >> 6;
        int q = g & 63;
        int col = (q < 32) ? q : (128 + q);      // [0,32) and [160,192)
        FA[a][col] = 0.f;
    }

    // interior: lerp 16 filtered base frames -> 128 angle rows
    for (int e = tid; e < 16384; e += 256) {
        int a = e >> 7, w = e & 127;
        int t0 = a >> 3;
        float v = (float)(a & 7) * 0.125f;
        float f0 = g_Fbase[(size_t)(t0 * 1024 + s) * 128 + w];
        float f1 = g_Fbase[(size_t)((((t0 + 1) & 15) * 1024 + s)) * 128 + w];
        FA[a][32 + w] = f0 + v * (f1 - f0);
    }
    __syncthreads();

    // each thread: one x, 64 consecutive y
    int x  = tid >> 1;
    int y0 = (tid & 1) << 6;
    float xa = (float)x  - 63.5f;
    float yb = (float)y0 - 63.5f;

    float acc[64];
#pragma unroll
    for (int i = 0; i < 64; i++) acc[i] = 0.f;

    for (int a = 0; a < 128; a++) {
        float c  = sc[a];
        float sn = ss[a];
        // +63.5 detector center, +32 guard offset; u stays > 0 always
        float u0 = fmaf(xa, c, fmaf(yb, sn, 63.5f + 32.0f));
        const float* row = FA[a];
#pragma unroll
        for (int yy = 0; yy < 64; yy++) {
            float u  = fmaf((float)yy, sn, u0);
            float t  = u + 8388607.5f;                 // 2^23 - 0.5: RN -> floor
            int   it = __float_as_int(t) - 0x4B000000; // floor(u) as int
            float fl = t - 8388608.0f;                 // floor(u) as float (exact)
            float fr = u - fl;                         // frac (Sterbenz exact)
            float g0 = row[it];
            float g1 = row[it + 1];
            acc[yy] += g0 + fr * (g1 - g0);
        }
    }

    float* op = out + (size_t)s * 16384 + x * 128 + y0;
#pragma unroll
    for (int yy = 0; yy < 64; yy += 4) {
        float4 v4 = make_float4(acc[yy], acc[yy + 1], acc[yy + 2], acc[yy + 3]);
        *(float4*)(op + yy) = v4;
    }
}

// ----------------------------------------------------------------------------
extern "C" void kernel_launch(void* const* d_in, const int* in_sizes, int n_in,
                              void* d_out, int out_size) {
    (void)in_sizes; (void)n_in; (void)out_size;
    const float* feat = (const float*)d_in[0];
    float* out = (float*)d_out;

    cudaFuncSetAttribute(k_bp, cudaFuncAttributeMaxDynamicSharedMemorySize,
                         128 * 192 * (int)sizeof(float));

    k_tables<<<1, 128>>>();
    k_filter<<<2048, 256>>>(feat);
    k_bp<<<1024, 256, 128 * 192 * sizeof(float)>>>(out);
}